// round 11
// baseline (speedup 1.0000x reference)
#include <cuda_runtime.h>
#include <cuda_bf16.h>
#include <cuda_fp8.h>
#include <math.h>
#include <stdint.h>

#define NN   50000
#define EE   800000
#define DIN  256
#define DH   128

// ---------------- scratch (static device globals; no allocation) ----------------
__device__ __align__(16) uint8_t g_msg1f8[(size_t)NN * DH];        // fp8 e4m3 messages L0
__device__ __align__(16) uint8_t g_msg2f8[(size_t)NN * DH];        // fp8 e4m3 messages L1
__device__ __align__(16) __nv_bfloat16 g_C1r[(size_t)NN * 256];    // bf16: r0 | proj
__device__ __align__(16) __nv_bfloat16 g_C2r[(size_t)NN * 128];    // bf16: r1
__device__ __align__(16) __nv_bfloat16 g_h1b[(size_t)NN * DH];     // h1 in bf16
__device__ __align__(16) __nv_bfloat16 g_h2b[(size_t)NN * DH];     // h2 in bf16
__device__ int g_deg[NN];
__device__ int g_rowptr[NN + 1];
__device__ int g_cursor[NN];
__device__ int g_csr_src[EE];
__device__ int g_bsum[64];
__device__ __align__(16) uint32_t g_Bp1b[(DIN / 2) * 384];         // bf16 pairs [kpair][384]
__device__ __align__(16) uint32_t g_Bp2b[(DH / 2) * 256];          // bf16 pairs [kpair][256]

// ---------------- side-stream resources ----------------
static cudaStream_t g_s2 = nullptr;
static cudaEvent_t  g_evFork = nullptr, g_evJoin = nullptr;
namespace {
struct InitRes {
    InitRes() {
        cudaStreamCreateWithFlags(&g_s2, cudaStreamNonBlocking);
        cudaEventCreateWithFlags(&g_evFork, cudaEventDisableTiming);
        cudaEventCreateWithFlags(&g_evJoin, cudaEventDisableTiming);
    }
};
static InitRes g_initres;
}

// ---------------- pack weights to bf16 k-pair layout ----------------
__global__ void pack_kernel(const float* __restrict__ Wl0, const float* __restrict__ Wr0,
                            const float* __restrict__ Wp,
                            const float* __restrict__ Wl1, const float* __restrict__ Wr1) {
    int idx = blockIdx.x * blockDim.x + threadIdx.x;
    if (idx < (DIN / 2) * 384) {
        int kp = idx / 384, j = idx % 384;
        int k0 = 2 * kp, k1 = 2 * kp + 1;
        float lo, hi;
        if (j < 128)      { lo = Wl0[k0 * DH + j];        hi = Wl0[k1 * DH + j]; }
        else if (j < 256) { lo = Wr0[k0 * DH + j - 128];  hi = Wr0[k1 * DH + j - 128]; }
        else              { lo = Wp [k0 * DH + j - 256];  hi = Wp [k1 * DH + j - 256]; }
        __nv_bfloat162 p = __floats2bfloat162_rn(lo, hi);
        g_Bp1b[idx] = *reinterpret_cast<uint32_t*>(&p);
    }
    if (idx < (DH / 2) * 256) {
        int kp = idx / 256, j = idx % 256;
        int k0 = 2 * kp, k1 = 2 * kp + 1;
        float lo, hi;
        if (j < 128) { lo = Wl1[k0 * DH + j];       hi = Wl1[k1 * DH + j]; }
        else         { lo = Wr1[k0 * DH + j - 128]; hi = Wr1[k1 * DH + j - 128]; }
        __nv_bfloat162 p = __floats2bfloat162_rn(lo, hi);
        g_Bp2b[idx] = *reinterpret_cast<uint32_t*>(&p);
    }
}

// ---------------- CSR build chain (side stream) ----------------
__global__ void zero_deg(int N) {
    int i = blockIdx.x * blockDim.x + threadIdx.x;
    if (i < N) g_deg[i] = 0;
}

__global__ void hist_kernel(const int* __restrict__ dst, int E) {
    int e = blockIdx.x * blockDim.x + threadIdx.x;
    if (e < E) atomicAdd(&g_deg[dst[e]], 1);
}

__global__ __launch_bounds__(1024)
void scan_blocks(int N) {
    __shared__ int wsum[32];
    int lane = threadIdx.x & 31, wid = threadIdx.x >> 5;
    int idx = blockIdx.x * 1024 + threadIdx.x;
    int v = (idx < N) ? g_deg[idx] : 0;
    int x = v;
#pragma unroll
    for (int o = 1; o < 32; o <<= 1) {
        int y = __shfl_up_sync(0xffffffffu, x, o);
        if (lane >= o) x += y;
    }
    if (lane == 31) wsum[wid] = x;
    __syncthreads();
    if (wid == 0) {
        int s = wsum[lane];
#pragma unroll
        for (int o = 1; o < 32; o <<= 1) {
            int y = __shfl_up_sync(0xffffffffu, s, o);
            if (lane >= o) s += y;
        }
        wsum[lane] = s;
    }
    __syncthreads();
    int excl = x - v + (wid > 0 ? wsum[wid - 1] : 0);
    if (idx < N) g_rowptr[idx] = excl;
    if (threadIdx.x == 1023) g_bsum[blockIdx.x] = excl + v;
}

__global__ void scan_add_fused(int N) {
    __shared__ int pre_s;
    int grp = blockIdx.x >> 2;
    if (threadIdx.x < 32) {
        int s = 0;
        for (int g = threadIdx.x; g < grp; g += 32) s += g_bsum[g];
#pragma unroll
        for (int o = 16; o; o >>= 1) s += __shfl_xor_sync(0xffffffffu, s, o);
        if (threadIdx.x == 0) pre_s = s;
    }
    __syncthreads();
    int i = blockIdx.x * 256 + threadIdx.x;
    if (i < N) {
        int r = g_rowptr[i] + pre_s;
        g_rowptr[i] = r;
        g_cursor[i] = r;
        if (i == N - 1) g_rowptr[N] = r + g_deg[N - 1];
    }
}

__global__ void csr_fill(const int* __restrict__ src, const int* __restrict__ dst, int E) {
    int e = blockIdx.x * blockDim.x + threadIdx.x;
    if (e >= E) return;
    int slot = atomicAdd(&g_cursor[dst[e]], 1);
    g_csr_src[slot] = src[e];
}

// ---------------- fp8 helpers ----------------
__device__ __forceinline__ uint16_t packf8(float a, float b) {
    // low byte = a, high byte = b (mirror of CVT_BF16X2_F32 operand order)
    uint16_t r;
    asm("cvt.rn.satfinite.e4m3x2.f32 %0, %1, %2;" : "=h"(r) : "f"(b), "f"(a));
    return r;
}

// ---------------- bf16 tensor-core GEMM (m16n8k16), double-buffered ----------------
// Column block 0 -> fp8 msg buffer (row stride 128 bytes).
// Other column blocks -> bf16 residual buffer at (col - 128), row stride residStride.
#define SPAD 136

__device__ __forceinline__ void mma_bf16(float c[4], uint32_t a0, uint32_t a1,
                                         uint32_t a2, uint32_t a3,
                                         uint32_t b0, uint32_t b1) {
    asm volatile(
        "mma.sync.aligned.m16n8k16.row.col.f32.bf16.bf16.f32 "
        "{%0,%1,%2,%3}, {%4,%5,%6,%7}, {%8,%9}, {%0,%1,%2,%3};"
        : "+f"(c[0]), "+f"(c[1]), "+f"(c[2]), "+f"(c[3])
        : "r"(a0), "r"(a1), "r"(a2), "r"(a3), "r"(b0), "r"(b1));
}

__device__ __forceinline__ uint32_t packbf(float lo, float hi) {
    __nv_bfloat162 p = __floats2bfloat162_rn(lo, hi);
    return *reinterpret_cast<uint32_t*>(&p);
}

__device__ __forceinline__ void loadA16(const __nv_bfloat16* p, uint4& r0, uint4& r1) {
    r0 = *(const uint4*)p;
    r1 = *(const uint4*)(p + 8);
}
__device__ __forceinline__ void loadA16(const float* p, uint4& r0, uint4& r1) {
    float4 a = ((const float4*)p)[0];
    float4 b = ((const float4*)p)[1];
    float4 c = ((const float4*)p)[2];
    float4 d = ((const float4*)p)[3];
    r0.x = packbf(a.x, a.y); r0.y = packbf(a.z, a.w);
    r0.z = packbf(b.x, b.y); r0.w = packbf(b.z, b.w);
    r1.x = packbf(c.x, c.y); r1.y = packbf(c.z, c.w);
    r1.z = packbf(d.x, d.y); r1.w = packbf(d.z, d.w);
}

template <typename AT>
__global__ __launch_bounds__(256)
void gemm_bf16(const AT* __restrict__ A, const uint32_t* __restrict__ Bp,
               uint8_t* __restrict__ msg8, __nv_bfloat16* __restrict__ resid,
               int residStride, int M, int K, int Ncol) {
    __shared__ uint32_t As[2][16][SPAD];
    __shared__ uint32_t Bs[2][16][SPAD];

    const int t = threadIdx.x;
    const int lane = t & 31;
    const int warp = t >> 5;
    const int wm = (warp & 1) * 64;
    const int wn = (warp >> 1) * 32;
    const int g = lane >> 2;
    const int t4 = lane & 3;

    const int rowBase = blockIdx.y * 128;
    const int colBase = blockIdx.x * 128;

    const int ar = t & 127;
    const int ah = t >> 7;
    const int bkp = t >> 4;
    const int bcol = (t & 15) * 8;

    float acc[4][4][4];
#pragma unroll
    for (int mt = 0; mt < 4; mt++)
#pragma unroll
        for (int nt = 0; nt < 4; nt++)
#pragma unroll
            for (int i = 0; i < 4; i++) acc[mt][nt][i] = 0.f;

    const int grow = rowBase + ar;
    const bool arow_ok = (grow < M);
    const AT* aBase = A + (size_t)grow * K + ah * 16;
    const uint32_t* bBase = Bp + (size_t)bkp * Ncol + colBase + bcol;

    uint4 ra0, ra1, rb0, rb1;

    if (arow_ok) loadA16(aBase, ra0, ra1);
    else { ra0 = make_uint4(0, 0, 0, 0); ra1 = make_uint4(0, 0, 0, 0); }
    rb0 = *(const uint4*)(bBase);
    rb1 = *(const uint4*)(bBase + 4);
    {
        const int kb = ah * 8;
        As[0][kb + 0][ar] = ra0.x; As[0][kb + 1][ar] = ra0.y;
        As[0][kb + 2][ar] = ra0.z; As[0][kb + 3][ar] = ra0.w;
        As[0][kb + 4][ar] = ra1.x; As[0][kb + 5][ar] = ra1.y;
        As[0][kb + 6][ar] = ra1.z; As[0][kb + 7][ar] = ra1.w;
        *(uint4*)&Bs[0][bkp][bcol]     = rb0;
        *(uint4*)&Bs[0][bkp][bcol + 4] = rb1;
    }
    __syncthreads();

    const int nChunks = K >> 5;
    for (int ci = 0; ci < nChunks; ci++) {
        const int cur = ci & 1;
        const int nxt = cur ^ 1;
        const bool more = (ci + 1 < nChunks);

        if (more) {
            int k0 = (ci + 1) << 5;
            if (arow_ok) loadA16(aBase + k0, ra0, ra1);
            rb0 = *(const uint4*)(bBase + (size_t)(k0 >> 1) * Ncol);
            rb1 = *(const uint4*)(bBase + (size_t)(k0 >> 1) * Ncol + 4);
        }

#pragma unroll
        for (int kk = 0; kk < 2; kk++) {
            const int kb = kk * 8;
            uint32_t af[4][4];
#pragma unroll
            for (int mt = 0; mt < 4; mt++) {
                int r = wm + mt * 16 + g;
                af[mt][0] = As[cur][kb + t4][r];
                af[mt][1] = As[cur][kb + t4][r + 8];
                af[mt][2] = As[cur][kb + t4 + 4][r];
                af[mt][3] = As[cur][kb + t4 + 4][r + 8];
            }
#pragma unroll
            for (int nt = 0; nt < 4; nt++) {
                int cn = wn + nt * 8 + g;
                uint32_t b0 = Bs[cur][kb + t4][cn];
                uint32_t b1 = Bs[cur][kb + t4 + 4][cn];
#pragma unroll
                for (int mt = 0; mt < 4; mt++)
                    mma_bf16(acc[mt][nt], af[mt][0], af[mt][1], af[mt][2], af[mt][3], b0, b1);
            }
        }

        if (more) {
            const int kb = ah * 8;
            As[nxt][kb + 0][ar] = ra0.x; As[nxt][kb + 1][ar] = ra0.y;
            As[nxt][kb + 2][ar] = ra0.z; As[nxt][kb + 3][ar] = ra0.w;
            As[nxt][kb + 4][ar] = ra1.x; As[nxt][kb + 5][ar] = ra1.y;
            As[nxt][kb + 6][ar] = ra1.z; As[nxt][kb + 7][ar] = ra1.w;
            *(uint4*)&Bs[nxt][bkp][bcol]     = rb0;
            *(uint4*)&Bs[nxt][bkp][bcol + 4] = rb1;
            __syncthreads();
        }
    }

    // epilogue
    const bool to_msg = (colBase == 0);
#pragma unroll
    for (int mt = 0; mt < 4; mt++) {
        int r0 = rowBase + wm + mt * 16 + g;
#pragma unroll
        for (int nt = 0; nt < 4; nt++) {
            int col = colBase + wn + nt * 8 + 2 * t4;
            if (to_msg) {
                if (r0 < M)
                    *(uint16_t*)(msg8 + (size_t)r0 * DH + col) =
                        packf8(acc[mt][nt][0], acc[mt][nt][1]);
                if (r0 + 8 < M)
                    *(uint16_t*)(msg8 + (size_t)(r0 + 8) * DH + col) =
                        packf8(acc[mt][nt][2], acc[mt][nt][3]);
            } else {
                int rc = col - 128;
                if (r0 < M)
                    *(__nv_bfloat162*)(resid + (size_t)r0 * residStride + rc) =
                        __floats2bfloat162_rn(acc[mt][nt][0], acc[mt][nt][1]);
                if (r0 + 8 < M)
                    *(__nv_bfloat162*)(resid + (size_t)(r0 + 8) * residStride + rc) =
                        __floats2bfloat162_rn(acc[mt][nt][2], acc[mt][nt][3]);
            }
        }
    }
}

// ---------------- decode helpers ----------------
__device__ __forceinline__ void bf4(uint2 u, float& f0, float& f1, float& f2, float& f3) {
    float2 p0 = __bfloat1622float2(*reinterpret_cast<__nv_bfloat162*>(&u.x));
    float2 p1 = __bfloat1622float2(*reinterpret_cast<__nv_bfloat162*>(&u.y));
    f0 = p0.x; f1 = p0.y; f2 = p1.x; f3 = p1.y;
}
// accumulate 4 fp8 (e4m3) values packed in a uint32
__device__ __forceinline__ void acc4_f8(uint32_t u, float& a0, float& a1, float& a2, float& a3) {
    uint32_t h0, h1;
    asm("cvt.rn.f16x2.e4m3x2 %0, %1;" : "=r"(h0) : "h"((uint16_t)(u & 0xffffu)));
    asm("cvt.rn.f16x2.e4m3x2 %0, %1;" : "=r"(h1) : "h"((uint16_t)(u >> 16)));
    float2 f0 = __half22float2(*reinterpret_cast<__half2*>(&h0));
    float2 f1 = __half22float2(*reinterpret_cast<__half2*>(&h1));
    a0 += f0.x; a1 += f0.y; a2 += f1.x; a3 += f1.y;
}

// ---------------- pull-aggregation, layer 0 (fp8 msgs, bf16 residuals) ----------------
__global__ __launch_bounds__(256)
void agg0_kernel(const float* __restrict__ bl0, const float* __restrict__ bp, int N) {
    int w = (blockIdx.x * blockDim.x + threadIdx.x) >> 5;
    int lane = threadIdx.x & 31;
    if (w >= N) return;
    int nbeg = g_rowptr[w], nend = g_rowptr[w + 1];
    float a0 = 0.f, a1 = 0.f, a2 = 0.f, a3 = 0.f;
    int j = nbeg;
    for (; j + 4 <= nend; j += 4) {
        uint32_t v0 = *((const uint32_t*)(g_msg1f8 + (size_t)g_csr_src[j + 0] * DH) + lane);
        uint32_t v1 = *((const uint32_t*)(g_msg1f8 + (size_t)g_csr_src[j + 1] * DH) + lane);
        uint32_t v2 = *((const uint32_t*)(g_msg1f8 + (size_t)g_csr_src[j + 2] * DH) + lane);
        uint32_t v3 = *((const uint32_t*)(g_msg1f8 + (size_t)g_csr_src[j + 3] * DH) + lane);
        acc4_f8(v0, a0, a1, a2, a3); acc4_f8(v1, a0, a1, a2, a3);
        acc4_f8(v2, a0, a1, a2, a3); acc4_f8(v3, a0, a1, a2, a3);
    }
    for (; j < nend; j++) {
        uint32_t v = *((const uint32_t*)(g_msg1f8 + (size_t)g_csr_src[j] * DH) + lane);
        acc4_f8(v, a0, a1, a2, a3);
    }
    float dinv = 1.0f / fmaxf((float)(nend - nbeg), 1.0f);
    float r0, r1, r2, r3, p0, p1, p2, p3;
    bf4(*(const uint2*)(g_C1r + (size_t)w * 256 + lane * 4), r0, r1, r2, r3);
    bf4(*(const uint2*)(g_C1r + (size_t)w * 256 + 128 + lane * 4), p0, p1, p2, p3);
    float4 bl = *(const float4*)(bl0 + lane * 4);
    float4 bv = *(const float4*)(bp + lane * 4);
    float o0 = fmaxf(fmaf(a0, dinv, bl.x + r0), 0.f) + p0 + bv.x;
    float o1 = fmaxf(fmaf(a1, dinv, bl.y + r1), 0.f) + p1 + bv.y;
    float o2 = fmaxf(fmaf(a2, dinv, bl.z + r2), 0.f) + p2 + bv.z;
    float o3 = fmaxf(fmaf(a3, dinv, bl.w + r3), 0.f) + p3 + bv.w;
    __nv_bfloat162 q0 = __floats2bfloat162_rn(o0, o1);
    __nv_bfloat162 q1 = __floats2bfloat162_rn(o2, o3);
    uint2 qo; qo.x = *reinterpret_cast<uint32_t*>(&q0); qo.y = *reinterpret_cast<uint32_t*>(&q1);
    *((uint2*)(g_h1b + (size_t)w * DH) + lane) = qo;
}

// ---------------- pull-aggregation, layer 1 (fp8 msgs, bf16 residuals) ----------------
__global__ __launch_bounds__(256)
void agg1_kernel(const float* __restrict__ bl1, int N) {
    int w = (blockIdx.x * blockDim.x + threadIdx.x) >> 5;
    int lane = threadIdx.x & 31;
    if (w >= N) return;
    int nbeg = g_rowptr[w], nend = g_rowptr[w + 1];
    float a0 = 0.f, a1 = 0.f, a2 = 0.f, a3 = 0.f;
    int j = nbeg;
    for (; j + 4 <= nend; j += 4) {
        uint32_t v0 = *((const uint32_t*)(g_msg2f8 + (size_t)g_csr_src[j + 0] * DH) + lane);
        uint32_t v1 = *((const uint32_t*)(g_msg2f8 + (size_t)g_csr_src[j + 1] * DH) + lane);
        uint32_t v2 = *((const uint32_t*)(g_msg2f8 + (size_t)g_csr_src[j + 2] * DH) + lane);
        uint32_t v3 = *((const uint32_t*)(g_msg2f8 + (size_t)g_csr_src[j + 3] * DH) + lane);
        acc4_f8(v0, a0, a1, a2, a3); acc4_f8(v1, a0, a1, a2, a3);
        acc4_f8(v2, a0, a1, a2, a3); acc4_f8(v3, a0, a1, a2, a3);
    }
    for (; j < nend; j++) {
        uint32_t v = *((const uint32_t*)(g_msg2f8 + (size_t)g_csr_src[j] * DH) + lane);
        acc4_f8(v, a0, a1, a2, a3);
    }
    float dinv = 1.0f / fmaxf((float)(nend - nbeg), 1.0f);
    float r0, r1, r2, r3, h0, h1, h2, h3;
    bf4(*(const uint2*)(g_C2r + (size_t)w * 128 + lane * 4), r0, r1, r2, r3);
    bf4(*((const uint2*)(g_h1b + (size_t)w * DH) + lane), h0, h1, h2, h3);
    float4 bl = *(const float4*)(bl1 + lane * 4);
    float o0 = fmaxf(fmaf(a0, dinv, bl.x + r0), 0.f) + h0;
    float o1 = fmaxf(fmaf(a1, dinv, bl.y + r1), 0.f) + h1;
    float o2 = fmaxf(fmaf(a2, dinv, bl.z + r2), 0.f) + h2;
    float o3 = fmaxf(fmaf(a3, dinv, bl.w + r3), 0.f) + h3;
    __nv_bfloat162 q0 = __floats2bfloat162_rn(o0, o1);
    __nv_bfloat162 q1 = __floats2bfloat162_rn(o2, o3);
    uint2 qo; qo.x = *reinterpret_cast<uint32_t*>(&q0); qo.y = *reinterpret_cast<uint32_t*>(&q1);
    *((uint2*)(g_h2b + (size_t)w * DH) + lane) = qo;
}

// ---------------- MMA head: gnn = relu(h2b@W1 + b1)@W2 + b2; blend ----------------
__global__ __launch_bounds__(256)
void head_mma(const float* __restrict__ W1, const float* __restrict__ b1,
              const float* __restrict__ W2, const float* __restrict__ b2,
              const float* __restrict__ rer, const float* __restrict__ alogit,
              float* __restrict__ out, int N) {
    extern __shared__ uint32_t sm[];
    uint32_t* As = sm;
    uint32_t* Bs = sm + 9216;
    float* Cs = (float*)sm;
    __shared__ float b1s[64];
    __shared__ float W2s[64];

    const int t = threadIdx.x;
    const int lane = t & 31;
    const int warp = t >> 5;
    const int wm = (warp & 1) * 64;
    const int wn = (warp >> 1) * 16;
    const int g = lane >> 2;
    const int t4 = lane & 3;
    const int rowBase = blockIdx.x * 128;

    for (int idx = t; idx < 64 * 64; idx += 256) {
        int kp = idx >> 6, col = idx & 63;
        __nv_bfloat162 p = __floats2bfloat162_rn(W1[(2 * kp) * 64 + col],
                                                 W1[(2 * kp + 1) * 64 + col]);
        Bs[kp * 72 + col] = *reinterpret_cast<uint32_t*>(&p);
    }
    if (t < 64) { b1s[t] = b1[t]; W2s[t] = W2[t]; }

    {
        int row = t & 127;
        int half = t >> 7;
        bool ok = (rowBase + row) < N;
        const uint4* aRow = (const uint4*)(g_h2b + (size_t)(rowBase + row) * DH);
#pragma unroll
        for (int q = 0; q < 8; q++) {
            uint4 u = ok ? aRow[half * 8 + q] : make_uint4(0, 0, 0, 0);
            int kp = (half * 8 + q) * 4;
            As[(kp + 0) * SPAD + row] = u.x;
            As[(kp + 1) * SPAD + row] = u.y;
            As[(kp + 2) * SPAD + row] = u.z;
            As[(kp + 3) * SPAD + row] = u.w;
        }
    }
    __syncthreads();

    float acc[4][2][4];
#pragma unroll
    for (int mt = 0; mt < 4; mt++)
#pragma unroll
        for (int nt = 0; nt < 2; nt++)
#pragma unroll
            for (int i = 0; i < 4; i++) acc[mt][nt][i] = 0.f;

#pragma unroll
    for (int step = 0; step < 8; step++) {
        const int kb = step * 8;
        uint32_t af[4][4];
#pragma unroll
        for (int mt = 0; mt < 4; mt++) {
            int r = wm + mt * 16 + g;
            af[mt][0] = As[(kb + t4) * SPAD + r];
            af[mt][1] = As[(kb + t4) * SPAD + r + 8];
            af[mt][2] = As[(kb + t4 + 4) * SPAD + r];
            af[mt][3] = As[(kb + t4 + 4) * SPAD + r + 8];
        }
#pragma unroll
        for (int nt = 0; nt < 2; nt++) {
            int cn = wn + nt * 8 + g;
            uint32_t b0 = Bs[(kb + t4) * 72 + cn];
            uint32_t b1r = Bs[(kb + t4 + 4) * 72 + cn];
#pragma unroll
            for (int mt = 0; mt < 4; mt++)
                mma_bf16(acc[mt][nt], af[mt][0], af[mt][1], af[mt][2], af[mt][3], b0, b1r);
        }
    }
    __syncthreads();

#pragma unroll
    for (int mt = 0; mt < 4; mt++) {
        int r = wm + mt * 16 + g;
#pragma unroll
        for (int nt = 0; nt < 2; nt++) {
            int col = wn + nt * 8 + 2 * t4;
            Cs[r * 72 + col]       = acc[mt][nt][0];
            Cs[r * 72 + col + 1]   = acc[mt][nt][1];
            Cs[(r + 8) * 72 + col]     = acc[mt][nt][2];
            Cs[(r + 8) * 72 + col + 1] = acc[mt][nt][3];
        }
    }
    __syncthreads();

    {
        int row = t >> 1;
        int hc = (t & 1) * 32;
        float s = 0.f;
#pragma unroll
        for (int c = 0; c < 32; c++) {
            int col = hc + c;
            s = fmaf(fmaxf(Cs[row * 72 + col] + b1s[col], 0.f), W2s[col], s);
        }
        s += __shfl_xor_sync(0xffffffffu, s, 1);
        int gr = rowBase + row;
        if ((t & 1) == 0 && gr < N) {
            float gnn = s + b2[0];
            float alpha = 1.0f / (1.0f + __expf(-alogit[0]));
            out[gr] = alpha * rer[gr] + (1.0f - alpha) * gnn;
        }
    }
}

// ---------------- launch ----------------
extern "C" void kernel_launch(void* const* d_in, const int* in_sizes, int n_in,
                              void* d_out, int out_size) {
    const float* x     = (const float*)d_in[0];
    const int*   eidx  = (const int*)d_in[1];
    const float* rer   = (const float*)d_in[2];
    const float* Wp    = (const float*)d_in[3];
    const float* bp    = (const float*)d_in[4];
    const float* Wl0   = (const float*)d_in[5];
    const float* bl0   = (const float*)d_in[6];
    const float* Wr0   = (const float*)d_in[7];
    const float* Wl1   = (const float*)d_in[8];
    const float* bl1   = (const float*)d_in[9];
    const float* Wr1   = (const float*)d_in[10];
    const float* W1    = (const float*)d_in[11];
    const float* b1    = (const float*)d_in[12];
    const float* W2    = (const float*)d_in[13];
    const float* b2    = (const float*)d_in[14];
    const float* alog  = (const float*)d_in[15];
    float* out = (float*)d_out;

    const int N = in_sizes[0] / DIN;       // 50000
    const int E = in_sizes[1] / 2;         // 800000
    const int* src = eidx;
    const int* dst = eidx + E;

    uint8_t *msg1f8, *msg2f8;
    __nv_bfloat16 *C1r, *C2r, *h1b;
    uint32_t *Bp1b, *Bp2b;
    cudaGetSymbolAddress((void**)&msg1f8, g_msg1f8);
    cudaGetSymbolAddress((void**)&msg2f8, g_msg2f8);
    cudaGetSymbolAddress((void**)&C1r,  g_C1r);
    cudaGetSymbolAddress((void**)&C2r,  g_C2r);
    cudaGetSymbolAddress((void**)&h1b,  g_h1b);
    cudaGetSymbolAddress((void**)&Bp1b, g_Bp1b);
    cudaGetSymbolAddress((void**)&Bp2b, g_Bp2b);

    static int init_done = 0;
    if (!init_done) {
        cudaFuncSetAttribute(head_mma, cudaFuncAttributeMaxDynamicSharedMemorySize, 55296);
        if (!g_s2) {
            cudaStreamCreateWithFlags(&g_s2, cudaStreamNonBlocking);
            cudaEventCreateWithFlags(&g_evFork, cudaEventDisableTiming);
            cudaEventCreateWithFlags(&g_evJoin, cudaEventDisableTiming);
        }
        init_done = 1;
    }

    // ---- fork side stream for CSR build ----
    cudaEventRecord(g_evFork, 0);
    cudaStreamWaitEvent(g_s2, g_evFork, 0);

    zero_deg<<<(N + 255) / 256, 256, 0, g_s2>>>(N);
    hist_kernel<<<(E + 255) / 256, 256, 0, g_s2>>>(dst, E);
    int nb = (N + 1023) / 1024;
    scan_blocks<<<nb, 1024, 0, g_s2>>>(N);
    scan_add_fused<<<(N + 255) / 256, 256, 0, g_s2>>>(N);
    csr_fill<<<(E + 255) / 256, 256, 0, g_s2>>>(src, dst, E);
    cudaEventRecord(g_evJoin, g_s2);

    // ---- main stream: pack, GEMM1 (fp32 A, convert fused) ----
    pack_kernel<<<((DIN / 2) * 384 + 255) / 256, 256>>>(Wl0, Wr0, Wp, Wl1, Wr1);
    {
        dim3 grid(384 / 128, (N + 127) / 128);
        gemm_bf16<float><<<grid, 256>>>(x, Bp1b, msg1f8, C1r, 256, N, DIN, 384);
    }

    // ---- join: agg0 needs CSR + GEMM1 ----
    cudaStreamWaitEvent(0, g_evJoin, 0);
    agg0_kernel<<<(N * 32 + 255) / 256, 256>>>(bl0, bp, N);

    // GEMM2 (bf16 A)
    {
        dim3 grid(256 / 128, (N + 127) / 128);
        gemm_bf16<__nv_bfloat16><<<grid, 256>>>(h1b, Bp2b, msg2f8, C2r, 128, N, DH, 256);
    }

    // pull-agg layer 1 + epilogue -> h2 bf16
    agg1_kernel<<<(N * 32 + 255) / 256, 256>>>(bl1, N);

    // MMA head + blend
    head_mma<<<(N + 127) / 128, 256, 55296>>>(W1, b1, W2, b2, rer, alog, out, N);
}

// round 13
// speedup vs baseline: 1.0248x; 1.0248x over previous
#include <cuda_runtime.h>
#include <cuda_bf16.h>
#include <cuda_fp8.h>
#include <math.h>
#include <stdint.h>

#define NN   50000
#define EE   800000
#define DIN  256
#define DH   128

// ---------------- scratch (static device globals; no allocation) ----------------
__device__ __align__(16) uint8_t g_msg1f8[(size_t)NN * DH];        // fp8 e4m3 messages L0
__device__ __align__(16) uint8_t g_msg2f8[(size_t)NN * DH];        // fp8 e4m3 messages L1
__device__ __align__(16) __nv_bfloat16 g_C1r[(size_t)NN * 256];    // bf16: r0 | proj
__device__ __align__(16) __nv_bfloat16 g_C2r[(size_t)NN * 128];    // bf16: r1
__device__ __align__(16) __nv_bfloat16 g_h1b[(size_t)NN * DH];     // h1 in bf16
__device__ __align__(16) __nv_bfloat16 g_h2b[(size_t)NN * DH];     // h2 in bf16
__device__ int g_deg[NN];
__device__ int g_rowptr[NN];        // segment start (unordered blocks, disjoint)
__device__ int g_cursor[NN];
__device__ int g_csr_src[EE];
__device__ int g_total;
__device__ __align__(16) uint32_t g_Bp1b[(DIN / 2) * 384];         // bf16 pairs [kpair][384]
__device__ __align__(16) uint32_t g_Bp2b[(DH / 2) * 256];          // bf16 pairs [kpair][256]

// ---------------- side-stream resources ----------------
static cudaStream_t g_s2 = nullptr;
static cudaEvent_t  g_evFork = nullptr, g_evJoin = nullptr;
namespace {
struct InitRes {
    InitRes() {
        cudaStreamCreateWithFlags(&g_s2, cudaStreamNonBlocking);
        cudaEventCreateWithFlags(&g_evFork, cudaEventDisableTiming);
        cudaEventCreateWithFlags(&g_evJoin, cudaEventDisableTiming);
    }
};
static InitRes g_initres;
}

// ---------------- pack weights + zero deg/total ----------------
// NOTE: must be launched with >= max((DIN/2)*384, NN) threads so g_deg is fully zeroed.
__global__ void pack_kernel(const float* __restrict__ Wl0, const float* __restrict__ Wr0,
                            const float* __restrict__ Wp,
                            const float* __restrict__ Wl1, const float* __restrict__ Wr1) {
    int idx = blockIdx.x * blockDim.x + threadIdx.x;
    if (idx < (DIN / 2) * 384) {
        int kp = idx / 384, j = idx % 384;
        int k0 = 2 * kp, k1 = 2 * kp + 1;
        float lo, hi;
        if (j < 128)      { lo = Wl0[k0 * DH + j];        hi = Wl0[k1 * DH + j]; }
        else if (j < 256) { lo = Wr0[k0 * DH + j - 128];  hi = Wr0[k1 * DH + j - 128]; }
        else              { lo = Wp [k0 * DH + j - 256];  hi = Wp [k1 * DH + j - 256]; }
        __nv_bfloat162 p = __floats2bfloat162_rn(lo, hi);
        g_Bp1b[idx] = *reinterpret_cast<uint32_t*>(&p);
    }
    if (idx < (DH / 2) * 256) {
        int kp = idx / 256, j = idx % 256;
        int k0 = 2 * kp, k1 = 2 * kp + 1;
        float lo, hi;
        if (j < 128) { lo = Wl1[k0 * DH + j];       hi = Wl1[k1 * DH + j]; }
        else         { lo = Wr1[k0 * DH + j - 128]; hi = Wr1[k1 * DH + j - 128]; }
        __nv_bfloat162 p = __floats2bfloat162_rn(lo, hi);
        g_Bp2b[idx] = *reinterpret_cast<uint32_t*>(&p);
    }
    if (idx < NN) g_deg[idx] = 0;
    if (idx == 0) g_total = 0;
}

// ---------------- CSR build (side stream) ----------------
__global__ void hist_kernel(const int* __restrict__ dst, int E) {
    int e = blockIdx.x * blockDim.x + threadIdx.x;
    if (e < E) atomicAdd(&g_deg[dst[e]], 1);
}

// per-block scan + atomic block base: rowptr[i] = base + local exclusive prefix
__global__ __launch_bounds__(1024)
void scan_assign(int N) {
    __shared__ int wsum[32];
    __shared__ int base_s;
    int lane = threadIdx.x & 31, wid = threadIdx.x >> 5;
    int idx = blockIdx.x * 1024 + threadIdx.x;
    int v = (idx < N) ? g_deg[idx] : 0;
    int x = v;
#pragma unroll
    for (int o = 1; o < 32; o <<= 1) {
        int y = __shfl_up_sync(0xffffffffu, x, o);
        if (lane >= o) x += y;
    }
    if (lane == 31) wsum[wid] = x;
    __syncthreads();
    if (wid == 0) {
        int s = wsum[lane];
#pragma unroll
        for (int o = 1; o < 32; o <<= 1) {
            int y = __shfl_up_sync(0xffffffffu, s, o);
            if (lane >= o) s += y;
        }
        wsum[lane] = s;
        if (lane == 31) base_s = atomicAdd(&g_total, s);
    }
    __syncthreads();
    int excl = x - v + (wid > 0 ? wsum[wid - 1] : 0) + base_s;
    if (idx < N) { g_rowptr[idx] = excl; g_cursor[idx] = excl; }
}

__global__ void csr_fill(const int* __restrict__ src, const int* __restrict__ dst, int E) {
    int e = blockIdx.x * blockDim.x + threadIdx.x;
    if (e >= E) return;
    int slot = atomicAdd(&g_cursor[dst[e]], 1);
    g_csr_src[slot] = src[e];
}

// ---------------- fp8 helpers ----------------
__device__ __forceinline__ uint16_t packf8(float a, float b) {
    uint16_t r;
    asm("cvt.rn.satfinite.e4m3x2.f32 %0, %1, %2;" : "=h"(r) : "f"(b), "f"(a));
    return r;
}

// ---------------- bf16 tensor-core GEMM (m16n8k16), double-buffered ----------------
#define SPAD 136

__device__ __forceinline__ void mma_bf16(float c[4], uint32_t a0, uint32_t a1,
                                         uint32_t a2, uint32_t a3,
                                         uint32_t b0, uint32_t b1) {
    asm volatile(
        "mma.sync.aligned.m16n8k16.row.col.f32.bf16.bf16.f32 "
        "{%0,%1,%2,%3}, {%4,%5,%6,%7}, {%8,%9}, {%0,%1,%2,%3};"
        : "+f"(c[0]), "+f"(c[1]), "+f"(c[2]), "+f"(c[3])
        : "r"(a0), "r"(a1), "r"(a2), "r"(a3), "r"(b0), "r"(b1));
}

__device__ __forceinline__ uint32_t packbf(float lo, float hi) {
    __nv_bfloat162 p = __floats2bfloat162_rn(lo, hi);
    return *reinterpret_cast<uint32_t*>(&p);
}

__device__ __forceinline__ void loadA16(const __nv_bfloat16* p, uint4& r0, uint4& r1) {
    r0 = *(const uint4*)p;
    r1 = *(const uint4*)(p + 8);
}
__device__ __forceinline__ void loadA16(const float* p, uint4& r0, uint4& r1) {
    float4 a = ((const float4*)p)[0];
    float4 b = ((const float4*)p)[1];
    float4 c = ((const float4*)p)[2];
    float4 d = ((const float4*)p)[3];
    r0.x = packbf(a.x, a.y); r0.y = packbf(a.z, a.w);
    r0.z = packbf(b.x, b.y); r0.w = packbf(b.z, b.w);
    r1.x = packbf(c.x, c.y); r1.y = packbf(c.z, c.w);
    r1.z = packbf(d.x, d.y); r1.w = packbf(d.z, d.w);
}

template <typename AT>
__global__ __launch_bounds__(256)
void gemm_bf16(const AT* __restrict__ A, const uint32_t* __restrict__ Bp,
               uint8_t* __restrict__ msg8, __nv_bfloat16* __restrict__ resid,
               int residStride, int M, int K, int Ncol) {
    __shared__ uint32_t As[2][16][SPAD];
    __shared__ uint32_t Bs[2][16][SPAD];

    const int t = threadIdx.x;
    const int lane = t & 31;
    const int warp = t >> 5;
    const int wm = (warp & 1) * 64;
    const int wn = (warp >> 1) * 32;
    const int g = lane >> 2;
    const int t4 = lane & 3;

    const int rowBase = blockIdx.y * 128;
    const int colBase = blockIdx.x * 128;

    const int ar = t & 127;
    const int ah = t >> 7;
    const int bkp = t >> 4;
    const int bcol = (t & 15) * 8;

    float acc[4][4][4];
#pragma unroll
    for (int mt = 0; mt < 4; mt++)
#pragma unroll
        for (int nt = 0; nt < 4; nt++)
#pragma unroll
            for (int i = 0; i < 4; i++) acc[mt][nt][i] = 0.f;

    const int grow = rowBase + ar;
    const bool arow_ok = (grow < M);
    const AT* aBase = A + (size_t)grow * K + ah * 16;
    const uint32_t* bBase = Bp + (size_t)bkp * Ncol + colBase + bcol;

    uint4 ra0, ra1, rb0, rb1;

    if (arow_ok) loadA16(aBase, ra0, ra1);
    else { ra0 = make_uint4(0, 0, 0, 0); ra1 = make_uint4(0, 0, 0, 0); }
    rb0 = *(const uint4*)(bBase);
    rb1 = *(const uint4*)(bBase + 4);
    {
        const int kb = ah * 8;
        As[0][kb + 0][ar] = ra0.x; As[0][kb + 1][ar] = ra0.y;
        As[0][kb + 2][ar] = ra0.z; As[0][kb + 3][ar] = ra0.w;
        As[0][kb + 4][ar] = ra1.x; As[0][kb + 5][ar] = ra1.y;
        As[0][kb + 6][ar] = ra1.z; As[0][kb + 7][ar] = ra1.w;
        *(uint4*)&Bs[0][bkp][bcol]     = rb0;
        *(uint4*)&Bs[0][bkp][bcol + 4] = rb1;
    }
    __syncthreads();

    const int nChunks = K >> 5;
    for (int ci = 0; ci < nChunks; ci++) {
        const int cur = ci & 1;
        const int nxt = cur ^ 1;
        const bool more = (ci + 1 < nChunks);

        if (more) {
            int k0 = (ci + 1) << 5;
            if (arow_ok) loadA16(aBase + k0, ra0, ra1);
            rb0 = *(const uint4*)(bBase + (size_t)(k0 >> 1) * Ncol);
            rb1 = *(const uint4*)(bBase + (size_t)(k0 >> 1) * Ncol + 4);
        }

#pragma unroll
        for (int kk = 0; kk < 2; kk++) {
            const int kb = kk * 8;
            uint32_t af[4][4];
#pragma unroll
            for (int mt = 0; mt < 4; mt++) {
                int r = wm + mt * 16 + g;
                af[mt][0] = As[cur][kb + t4][r];
                af[mt][1] = As[cur][kb + t4][r + 8];
                af[mt][2] = As[cur][kb + t4 + 4][r];
                af[mt][3] = As[cur][kb + t4 + 4][r + 8];
            }
#pragma unroll
            for (int nt = 0; nt < 4; nt++) {
                int cn = wn + nt * 8 + g;
                uint32_t b0 = Bs[cur][kb + t4][cn];
                uint32_t b1 = Bs[cur][kb + t4 + 4][cn];
#pragma unroll
                for (int mt = 0; mt < 4; mt++)
                    mma_bf16(acc[mt][nt], af[mt][0], af[mt][1], af[mt][2], af[mt][3], b0, b1);
            }
        }

        if (more) {
            const int kb = ah * 8;
            As[nxt][kb + 0][ar] = ra0.x; As[nxt][kb + 1][ar] = ra0.y;
            As[nxt][kb + 2][ar] = ra0.z; As[nxt][kb + 3][ar] = ra0.w;
            As[nxt][kb + 4][ar] = ra1.x; As[nxt][kb + 5][ar] = ra1.y;
            As[nxt][kb + 6][ar] = ra1.z; As[nxt][kb + 7][ar] = ra1.w;
            *(uint4*)&Bs[nxt][bkp][bcol]     = rb0;
            *(uint4*)&Bs[nxt][bkp][bcol + 4] = rb1;
            __syncthreads();
        }
    }

    const bool to_msg = (colBase == 0);
#pragma unroll
    for (int mt = 0; mt < 4; mt++) {
        int r0 = rowBase + wm + mt * 16 + g;
#pragma unroll
        for (int nt = 0; nt < 4; nt++) {
            int col = colBase + wn + nt * 8 + 2 * t4;
            if (to_msg) {
                if (r0 < M)
                    *(uint16_t*)(msg8 + (size_t)r0 * DH + col) =
                        packf8(acc[mt][nt][0], acc[mt][nt][1]);
                if (r0 + 8 < M)
                    *(uint16_t*)(msg8 + (size_t)(r0 + 8) * DH + col) =
                        packf8(acc[mt][nt][2], acc[mt][nt][3]);
            } else {
                int rc = col - 128;
                if (r0 < M)
                    *(__nv_bfloat162*)(resid + (size_t)r0 * residStride + rc) =
                        __floats2bfloat162_rn(acc[mt][nt][0], acc[mt][nt][1]);
                if (r0 + 8 < M)
                    *(__nv_bfloat162*)(resid + (size_t)(r0 + 8) * residStride + rc) =
                        __floats2bfloat162_rn(acc[mt][nt][2], acc[mt][nt][3]);
            }
        }
    }
}

// ---------------- decode helpers ----------------
__device__ __forceinline__ void bf4(uint2 u, float& f0, float& f1, float& f2, float& f3) {
    float2 p0 = __bfloat1622float2(*reinterpret_cast<__nv_bfloat162*>(&u.x));
    float2 p1 = __bfloat1622float2(*reinterpret_cast<__nv_bfloat162*>(&u.y));
    f0 = p0.x; f1 = p0.y; f2 = p1.x; f3 = p1.y;
}
__device__ __forceinline__ void acc4_f8(uint32_t u, float& a0, float& a1, float& a2, float& a3) {
    uint32_t h0, h1;
    asm("cvt.rn.f16x2.e4m3x2 %0, %1;" : "=r"(h0) : "h"((uint16_t)(u & 0xffffu)));
    asm("cvt.rn.f16x2.e4m3x2 %0, %1;" : "=r"(h1) : "h"((uint16_t)(u >> 16)));
    float2 f0 = __half22float2(*reinterpret_cast<__half2*>(&h0));
    float2 f1 = __half22float2(*reinterpret_cast<__half2*>(&h1));
    a0 += f0.x; a1 += f0.y; a2 += f1.x; a3 += f1.y;
}

// ---------------- pull-aggregation, layer 0 ----------------
__global__ __launch_bounds__(256)
void agg0_kernel(const float* __restrict__ bl0, const float* __restrict__ bp, int N) {
    int w = (blockIdx.x * blockDim.x + threadIdx.x) >> 5;
    int lane = threadIdx.x & 31;
    if (w >= N) return;
    int nbeg = g_rowptr[w];
    int dg = g_deg[w];
    int nend = nbeg + dg;
    float a0 = 0.f, a1 = 0.f, a2 = 0.f, a3 = 0.f;
    int j = nbeg;
    for (; j + 4 <= nend; j += 4) {
        uint32_t v0 = *((const uint32_t*)(g_msg1f8 + (size_t)g_csr_src[j + 0] * DH) + lane);
        uint32_t v1 = *((const uint32_t*)(g_msg1f8 + (size_t)g_csr_src[j + 1] * DH) + lane);
        uint32_t v2 = *((const uint32_t*)(g_msg1f8 + (size_t)g_csr_src[j + 2] * DH) + lane);
        uint32_t v3 = *((const uint32_t*)(g_msg1f8 + (size_t)g_csr_src[j + 3] * DH) + lane);
        acc4_f8(v0, a0, a1, a2, a3); acc4_f8(v1, a0, a1, a2, a3);
        acc4_f8(v2, a0, a1, a2, a3); acc4_f8(v3, a0, a1, a2, a3);
    }
    for (; j < nend; j++) {
        uint32_t v = *((const uint32_t*)(g_msg1f8 + (size_t)g_csr_src[j] * DH) + lane);
        acc4_f8(v, a0, a1, a2, a3);
    }
    float dinv = 1.0f / fmaxf((float)dg, 1.0f);
    float r0, r1, r2, r3, p0, p1, p2, p3;
    bf4(*(const uint2*)(g_C1r + (size_t)w * 256 + lane * 4), r0, r1, r2, r3);
    bf4(*(const uint2*)(g_C1r + (size_t)w * 256 + 128 + lane * 4), p0, p1, p2, p3);
    float4 bl = *(const float4*)(bl0 + lane * 4);
    float4 bv = *(const float4*)(bp + lane * 4);
    float o0 = fmaxf(fmaf(a0, dinv, bl.x + r0), 0.f) + p0 + bv.x;
    float o1 = fmaxf(fmaf(a1, dinv, bl.y + r1), 0.f) + p1 + bv.y;
    float o2 = fmaxf(fmaf(a2, dinv, bl.z + r2), 0.f) + p2 + bv.z;
    float o3 = fmaxf(fmaf(a3, dinv, bl.w + r3), 0.f) + p3 + bv.w;
    __nv_bfloat162 q0 = __floats2bfloat162_rn(o0, o1);
    __nv_bfloat162 q1 = __floats2bfloat162_rn(o2, o3);
    uint2 qo; qo.x = *reinterpret_cast<uint32_t*>(&q0); qo.y = *reinterpret_cast<uint32_t*>(&q1);
    *((uint2*)(g_h1b + (size_t)w * DH) + lane) = qo;
}

// ---------------- pull-aggregation, layer 1 ----------------
__global__ __launch_bounds__(256)
void agg1_kernel(const float* __restrict__ bl1, int N) {
    int w = (blockIdx.x * blockDim.x + threadIdx.x) >> 5;
    int lane = threadIdx.x & 31;
    if (w >= N) return;
    int nbeg = g_rowptr[w];
    int dg = g_deg[w];
    int nend = nbeg + dg;
    float a0 = 0.f, a1 = 0.f, a2 = 0.f, a3 = 0.f;
    int j = nbeg;
    for (; j + 4 <= nend; j += 4) {
        uint32_t v0 = *((const uint32_t*)(g_msg2f8 + (size_t)g_csr_src[j + 0] * DH) + lane);
        uint32_t v1 = *((const uint32_t*)(g_msg2f8 + (size_t)g_csr_src[j + 1] * DH) + lane);
        uint32_t v2 = *((const uint32_t*)(g_msg2f8 + (size_t)g_csr_src[j + 2] * DH) + lane);
        uint32_t v3 = *((const uint32_t*)(g_msg2f8 + (size_t)g_csr_src[j + 3] * DH) + lane);
        acc4_f8(v0, a0, a1, a2, a3); acc4_f8(v1, a0, a1, a2, a3);
        acc4_f8(v2, a0, a1, a2, a3); acc4_f8(v3, a0, a1, a2, a3);
    }
    for (; j < nend; j++) {
        uint32_t v = *((const uint32_t*)(g_msg2f8 + (size_t)g_csr_src[j] * DH) + lane);
        acc4_f8(v, a0, a1, a2, a3);
    }
    float dinv = 1.0f / fmaxf((float)dg, 1.0f);
    float r0, r1, r2, r3, h0, h1, h2, h3;
    bf4(*(const uint2*)(g_C2r + (size_t)w * 128 + lane * 4), r0, r1, r2, r3);
    bf4(*((const uint2*)(g_h1b + (size_t)w * DH) + lane), h0, h1, h2, h3);
    float4 bl = *(const float4*)(bl1 + lane * 4);
    float o0 = fmaxf(fmaf(a0, dinv, bl.x + r0), 0.f) + h0;
    float o1 = fmaxf(fmaf(a1, dinv, bl.y + r1), 0.f) + h1;
    float o2 = fmaxf(fmaf(a2, dinv, bl.z + r2), 0.f) + h2;
    float o3 = fmaxf(fmaf(a3, dinv, bl.w + r3), 0.f) + h3;
    __nv_bfloat162 q0 = __floats2bfloat162_rn(o0, o1);
    __nv_bfloat162 q1 = __floats2bfloat162_rn(o2, o3);
    uint2 qo; qo.x = *reinterpret_cast<uint32_t*>(&q0); qo.y = *reinterpret_cast<uint32_t*>(&q1);
    *((uint2*)(g_h2b + (size_t)w * DH) + lane) = qo;
}

// ---------------- MMA head: gnn = relu(h2b@W1 + b1)@W2 + b2; blend ----------------
__global__ __launch_bounds__(256)
void head_mma(const float* __restrict__ W1, const float* __restrict__ b1,
              const float* __restrict__ W2, const float* __restrict__ b2,
              const float* __restrict__ rer, const float* __restrict__ alogit,
              float* __restrict__ out, int N) {
    extern __shared__ uint32_t sm[];
    uint32_t* As = sm;
    uint32_t* Bs = sm + 9216;
    float* Cs = (float*)sm;
    __shared__ float b1s[64];
    __shared__ float W2s[64];

    const int t = threadIdx.x;
    const int lane = t & 31;
    const int warp = t >> 5;
    const int wm = (warp & 1) * 64;
    const int wn = (warp >> 1) * 16;
    const int g = lane >> 2;
    const int t4 = lane & 3;
    const int rowBase = blockIdx.x * 128;

    for (int idx = t; idx < 64 * 64; idx += 256) {
        int kp = idx >> 6, col = idx & 63;
        __nv_bfloat162 p = __floats2bfloat162_rn(W1[(2 * kp) * 64 + col],
                                                 W1[(2 * kp + 1) * 64 + col]);
        Bs[kp * 72 + col] = *reinterpret_cast<uint32_t*>(&p);
    }
    if (t < 64) { b1s[t] = b1[t]; W2s[t] = W2[t]; }

    {
        int row = t & 127;
        int half = t >> 7;
        bool ok = (rowBase + row) < N;
        const uint4* aRow = (const uint4*)(g_h2b + (size_t)(rowBase + row) * DH);
#pragma unroll
        for (int q = 0; q < 8; q++) {
            uint4 u = ok ? aRow[half * 8 + q] : make_uint4(0, 0, 0, 0);
            int kp = (half * 8 + q) * 4;
            As[(kp + 0) * SPAD + row] = u.x;
            As[(kp + 1) * SPAD + row] = u.y;
            As[(kp + 2) * SPAD + row] = u.z;
            As[(kp + 3) * SPAD + row] = u.w;
        }
    }
    __syncthreads();

    float acc[4][2][4];
#pragma unroll
    for (int mt = 0; mt < 4; mt++)
#pragma unroll
        for (int nt = 0; nt < 2; nt++)
#pragma unroll
            for (int i = 0; i < 4; i++) acc[mt][nt][i] = 0.f;

#pragma unroll
    for (int step = 0; step < 8; step++) {
        const int kb = step * 8;
        uint32_t af[4][4];
#pragma unroll
        for (int mt = 0; mt < 4; mt++) {
            int r = wm + mt * 16 + g;
            af[mt][0] = As[(kb + t4) * SPAD + r];
            af[mt][1] = As[(kb + t4) * SPAD + r + 8];
            af[mt][2] = As[(kb + t4 + 4) * SPAD + r];
            af[mt][3] = As[(kb + t4 + 4) * SPAD + r + 8];
        }
#pragma unroll
        for (int nt = 0; nt < 2; nt++) {
            int cn = wn + nt * 8 + g;
            uint32_t b0 = Bs[(kb + t4) * 72 + cn];
            uint32_t b1r = Bs[(kb + t4 + 4) * 72 + cn];
#pragma unroll
            for (int mt = 0; mt < 4; mt++)
                mma_bf16(acc[mt][nt], af[mt][0], af[mt][1], af[mt][2], af[mt][3], b0, b1r);
        }
    }
    __syncthreads();

#pragma unroll
    for (int mt = 0; mt < 4; mt++) {
        int r = wm + mt * 16 + g;
#pragma unroll
        for (int nt = 0; nt < 2; nt++) {
            int col = wn + nt * 8 + 2 * t4;
            Cs[r * 72 + col]       = acc[mt][nt][0];
            Cs[r * 72 + col + 1]   = acc[mt][nt][1];
            Cs[(r + 8) * 72 + col]     = acc[mt][nt][2];
            Cs[(r + 8) * 72 + col + 1] = acc[mt][nt][3];
        }
    }
    __syncthreads();

    {
        int row = t >> 1;
        int hc = (t & 1) * 32;
        float s = 0.f;
#pragma unroll
        for (int c = 0; c < 32; c++) {
            int col = hc + c;
            s = fmaf(fmaxf(Cs[row * 72 + col] + b1s[col], 0.f), W2s[col], s);
        }
        s += __shfl_xor_sync(0xffffffffu, s, 1);
        int gr = rowBase + row;
        if ((t & 1) == 0 && gr < N) {
            float gnn = s + b2[0];
            float alpha = 1.0f / (1.0f + __expf(-alogit[0]));
            out[gr] = alpha * rer[gr] + (1.0f - alpha) * gnn;
        }
    }
}

// ---------------- launch ----------------
extern "C" void kernel_launch(void* const* d_in, const int* in_sizes, int n_in,
                              void* d_out, int out_size) {
    const float* x     = (const float*)d_in[0];
    const int*   eidx  = (const int*)d_in[1];
    const float* rer   = (const float*)d_in[2];
    const float* Wp    = (const float*)d_in[3];
    const float* bp    = (const float*)d_in[4];
    const float* Wl0   = (const float*)d_in[5];
    const float* bl0   = (const float*)d_in[6];
    const float* Wr0   = (const float*)d_in[7];
    const float* Wl1   = (const float*)d_in[8];
    const float* bl1   = (const float*)d_in[9];
    const float* Wr1   = (const float*)d_in[10];
    const float* W1    = (const float*)d_in[11];
    const float* b1    = (const float*)d_in[12];
    const float* W2    = (const float*)d_in[13];
    const float* b2    = (const float*)d_in[14];
    const float* alog  = (const float*)d_in[15];
    float* out = (float*)d_out;

    const int N = in_sizes[0] / DIN;       // 50000
    const int E = in_sizes[1] / 2;         // 800000
    const int* src = eidx;
    const int* dst = eidx + E;

    uint8_t *msg1f8, *msg2f8;
    __nv_bfloat16 *C1r, *C2r, *h1b;
    uint32_t *Bp1b, *Bp2b;
    cudaGetSymbolAddress((void**)&msg1f8, g_msg1f8);
    cudaGetSymbolAddress((void**)&msg2f8, g_msg2f8);
    cudaGetSymbolAddress((void**)&C1r,  g_C1r);
    cudaGetSymbolAddress((void**)&C2r,  g_C2r);
    cudaGetSymbolAddress((void**)&h1b,  g_h1b);
    cudaGetSymbolAddress((void**)&Bp1b, g_Bp1b);
    cudaGetSymbolAddress((void**)&Bp2b, g_Bp2b);

    static int init_done = 0;
    if (!init_done) {
        cudaFuncSetAttribute(head_mma, cudaFuncAttributeMaxDynamicSharedMemorySize, 55296);
        if (!g_s2) {
            cudaStreamCreateWithFlags(&g_s2, cudaStreamNonBlocking);
            cudaEventCreateWithFlags(&g_evFork, cudaEventDisableTiming);
            cudaEventCreateWithFlags(&g_evJoin, cudaEventDisableTiming);
        }
        init_done = 1;
    }

    // (1) pack weights + zero deg/total — grid MUST cover max(pack work, N)
    {
        int nthr = (DIN / 2) * 384;            // 49152
        int cover = nthr > N ? nthr : N;       // 50000
        pack_kernel<<<(cover + 255) / 256, 256>>>(Wl0, Wr0, Wp, Wl1, Wr1);
    }

    // fork: CSR build on side stream (depends on pack's zeroing)
    cudaEventRecord(g_evFork, 0);
    cudaStreamWaitEvent(g_s2, g_evFork, 0);
    hist_kernel<<<(E + 255) / 256, 256, 0, g_s2>>>(dst, E);                // (2)
    scan_assign<<<(N + 1023) / 1024, 1024, 0, g_s2>>>(N);                  // (3)
    csr_fill<<<(E + 255) / 256, 256, 0, g_s2>>>(src, dst, E);              // (4)
    cudaEventRecord(g_evJoin, g_s2);

    // (5) GEMM1 on main (concurrent with CSR build)
    {
        dim3 grid(384 / 128, (N + 127) / 128);
        gemm_bf16<float><<<grid, 256>>>(x, Bp1b, msg1f8, C1r, 256, N, DIN, 384);
    }

    // join: agg0 needs CSR + GEMM1
    cudaStreamWaitEvent(0, g_evJoin, 0);
    agg0_kernel<<<(N * 32 + 255) / 256, 256>>>(bl0, bp, N);                // (6)

    // (7) GEMM2 (bf16 A)
    {
        dim3 grid(256 / 128, (N + 127) / 128);
        gemm_bf16<__nv_bfloat16><<<grid, 256>>>(h1b, Bp2b, msg2f8, C2r, 128, N, DH, 256);
    }

    // (8) pull-agg layer 1 -> h2 bf16
    agg1_kernel<<<(N * 32 + 255) / 256, 256>>>(bl1, N);

    // (9) MMA head + blend
    head_mma<<<(N + 127) / 128, 256, 55296>>>(W1, b1, W2, b2, rer, alog, out, N);
}